// round 1
// baseline (speedup 1.0000x reference)
#include <cuda_runtime.h>
#include <math.h>

#define N 4096
#define F 512
#define O 64
#define H 8
#define C 16
#define NW 128  // mask words per row (N/32)

// -------- scratch (static device globals; no allocation) --------
__device__ unsigned g_mask[N * NW];          // 2 MB bit-packed adjacency
__device__ float g_Wh[H * N * O];            // 8 MB
__device__ float g_E1p[H * N], g_E1n[H * N], g_E2p[H * N], g_E2n[H * N];
__device__ float g_hcat[N * F];              // 8 MB  (F == H*O)
__device__ float g_Who[N * C];
__device__ float g2_E1p[N], g2_E1n[N], g2_E2p[N], g2_E2n[N];

// ---------------- K0: pack adjacency to bits ----------------
__global__ void k_pack(const int* __restrict__ adj) {
    int gt = blockIdx.x * blockDim.x + threadIdx.x;
    int w = gt >> 5, lane = gt & 31;
    int i = w >> 7, jw = w & (NW - 1);
    int v = adj[i * N + jw * 32 + lane];
    unsigned m = __ballot_sync(0xffffffffu, v > 0);
    if (lane == 0) g_mask[w] = m;
}

// ---------------- K1: Wh[h] = x @ W[h]  (M=4096, K=512, N=64) ----------------
__global__ void __launch_bounds__(256) k_gemm1(const float* __restrict__ x,
                                               const float* __restrict__ W) {
    __shared__ float xs[64][33];
    __shared__ float4 ws[32][16];
    int h = blockIdx.y;
    int r0 = blockIdx.x * 64;
    int t = threadIdx.x;
    int ty = t >> 4, tx = t & 15;
    float4 acc[4];
#pragma unroll
    for (int r = 0; r < 4; ++r) acc[r] = make_float4(0.f, 0.f, 0.f, 0.f);

    for (int k0 = 0; k0 < F; k0 += 32) {
        for (int idx = t; idx < 64 * 32; idx += 256) {
            int r = idx >> 5, k = idx & 31;
            xs[r][k] = x[(r0 + r) * F + k0 + k];
        }
        for (int idx = t; idx < 32 * 64; idx += 256) {
            int k = idx >> 6, o = idx & 63;
            ((float*)ws)[k * 64 + o] = W[h * F * O + (k0 + k) * O + o];
        }
        __syncthreads();
#pragma unroll
        for (int k = 0; k < 32; ++k) {
            float4 wv = ws[k][tx];
#pragma unroll
            for (int r = 0; r < 4; ++r) {
                float xa = xs[ty * 4 + r][k];
                acc[r].x += xa * wv.x; acc[r].y += xa * wv.y;
                acc[r].z += xa * wv.z; acc[r].w += xa * wv.w;
            }
        }
        __syncthreads();
    }
#pragma unroll
    for (int r = 0; r < 4; ++r) {
        int row = r0 + ty * 4 + r;
        float* dst = g_Wh + (h * N + row) * O + tx * 4;
        dst[0] = acc[r].x; dst[1] = acc[r].y; dst[2] = acc[r].z; dst[3] = acc[r].w;
    }
}

// ---------------- K1b: per-node scores + factored exponentials (layer 1) ----------------
__global__ void k_scores1(const float* __restrict__ a) {
    int gw = (blockIdx.x * blockDim.x + threadIdx.x) >> 5;  // gw = h*N + n
    int lane = threadIdx.x & 31;
    int h = gw >> 12;
    const float* wh = g_Wh + gw * O;
    const float* ah = a + h * 2 * O;
    float w0 = wh[lane], w1 = wh[lane + 32];
    float v1 = w0 * ah[lane] + w1 * ah[lane + 32];
    float v2 = w0 * ah[O + lane] + w1 * ah[O + lane + 32];
#pragma unroll
    for (int off = 16; off; off >>= 1) {
        v1 += __shfl_down_sync(0xffffffffu, v1, off);
        v2 += __shfl_down_sync(0xffffffffu, v2, off);
    }
    if (lane == 0) {
        g_E1p[gw] = expf(v1);        g_E1n[gw] = expf(0.2f * v1);
        g_E2p[gw] = expf(v2);        g_E2n[gw] = expf(0.2f * v2);
    }
}

// ---------------- K2: layer-1 masked-softmax aggregate + ELU -> g_hcat ----------------
__global__ void __launch_bounds__(256) k_agg1() {
    __shared__ float4 whs[128][16];      // 32 KB: Wh j-tile
    __shared__ float e2ps[128], e2ns[128];
    __shared__ unsigned ms[64][4];
    int h = blockIdx.y;
    int r0 = blockIdx.x * 64;
    int t = threadIdx.x;
    int ty = t >> 4, tx = t & 15;

    float4 acc[4];
    float den[4];
    float e1p[4], e1n[4];
#pragma unroll
    for (int r = 0; r < 4; ++r) {
        acc[r] = make_float4(0.f, 0.f, 0.f, 0.f);
        den[r] = 0.f;
        int row = r0 + ty * 4 + r;
        e1p[r] = g_E1p[h * N + row];
        e1n[r] = g_E1n[h * N + row];
    }

    for (int j0 = 0; j0 < N; j0 += 128) {
        for (int idx = t; idx < 128 * 16; idx += 256) {
            int j = idx >> 4, c = idx & 15;
            whs[j][c] = *(const float4*)(g_Wh + (h * N + j0 + j) * O + c * 4);
        }
        if (t < 128) {
            e2ps[t] = g_E2p[h * N + j0 + t];
            e2ns[t] = g_E2n[h * N + j0 + t];
        }
        {
            int r = t >> 2, w = t & 3;
            ms[r][w] = g_mask[(r0 + r) * NW + (j0 >> 5) + w];
        }
        __syncthreads();
#pragma unroll 1
        for (int jw = 0; jw < 4; ++jw) {
            unsigned m0 = ms[ty * 4 + 0][jw];
            unsigned m1 = ms[ty * 4 + 1][jw];
            unsigned m2 = ms[ty * 4 + 2][jw];
            unsigned m3 = ms[ty * 4 + 3][jw];
#pragma unroll
            for (int b = 0; b < 32; ++b) {
                int jj = jw * 32 + b;
                float e2p = e2ps[jj], e2n = e2ns[jj];
                float4 wv = whs[jj][tx];
#define ROWSTEP(r, mreg)                                                   \
                {                                                          \
                    float wp = e1p[r] * e2p;                               \
                    float wgt = (wp >= 1.f) ? wp : (e1n[r] * e2n);         \
                    wgt = ((mreg >> b) & 1u) ? wgt : 0.f;                  \
                    den[r] += wgt;                                         \
                    acc[r].x += wgt * wv.x; acc[r].y += wgt * wv.y;        \
                    acc[r].z += wgt * wv.z; acc[r].w += wgt * wv.w;        \
                }
                ROWSTEP(0, m0) ROWSTEP(1, m1) ROWSTEP(2, m2) ROWSTEP(3, m3)
#undef ROWSTEP
            }
        }
        __syncthreads();
    }
#pragma unroll
    for (int r = 0; r < 4; ++r) {
        int row = r0 + ty * 4 + r;
        float inv = 1.f / den[r];
        float v[4] = {acc[r].x * inv, acc[r].y * inv, acc[r].z * inv, acc[r].w * inv};
#pragma unroll
        for (int k = 0; k < 4; ++k) v[k] = (v[k] > 0.f) ? v[k] : (expf(v[k]) - 1.f);
        float* dst = g_hcat + row * F + h * O + tx * 4;
        dst[0] = v[0]; dst[1] = v[1]; dst[2] = v[2]; dst[3] = v[3];
    }
}

// ---------------- K3a: Who = hcat @ W_out  (M=4096, K=512, N=16) ----------------
__global__ void __launch_bounds__(256) k_gemm2(const float* __restrict__ Wout) {
    __shared__ float hs[64][65];
    __shared__ float4 wos[64][4];
    int r0 = blockIdx.x * 64;
    int t = threadIdx.x;
    int row = t >> 2, cg = t & 3;
    float4 acc = make_float4(0.f, 0.f, 0.f, 0.f);
    for (int k0 = 0; k0 < F; k0 += 64) {
        for (int idx = t; idx < 64 * 64; idx += 256) {
            int r = idx >> 6, k = idx & 63;
            hs[r][k] = g_hcat[(r0 + r) * F + k0 + k];
        }
        for (int idx = t; idx < 64 * 16; idx += 256) {
            int k = idx >> 4, c = idx & 15;
            ((float*)wos)[k * 16 + c] = Wout[(k0 + k) * C + c];
        }
        __syncthreads();
#pragma unroll
        for (int k = 0; k < 64; ++k) {
            float hv = hs[row][k];
            float4 wv = wos[k][cg];
            acc.x += hv * wv.x; acc.y += hv * wv.y;
            acc.z += hv * wv.z; acc.w += hv * wv.w;
        }
        __syncthreads();
    }
    float* dst = g_Who + (r0 + row) * C + cg * 4;
    dst[0] = acc.x; dst[1] = acc.y; dst[2] = acc.z; dst[3] = acc.w;
}

// ---------------- K3b: per-node scores + exponentials (layer 2) ----------------
__global__ void k_scores2(const float* __restrict__ aout) {
    int gw = (blockIdx.x * blockDim.x + threadIdx.x) >> 5;  // node id
    int lane = threadIdx.x & 31;
    float v1 = 0.f, v2 = 0.f;
    if (lane < C) {
        float w = g_Who[gw * C + lane];
        v1 = w * aout[lane];
        v2 = w * aout[C + lane];
    }
#pragma unroll
    for (int off = 8; off; off >>= 1) {
        v1 += __shfl_down_sync(0xffffffffu, v1, off);
        v2 += __shfl_down_sync(0xffffffffu, v2, off);
    }
    if (lane == 0) {
        g2_E1p[gw] = expf(v1);       g2_E1n[gw] = expf(0.2f * v1);
        g2_E2p[gw] = expf(v2);       g2_E2n[gw] = expf(0.2f * v2);
    }
}

// ---------------- K4: layer-2 aggregate + ELU + log_softmax ----------------
__global__ void __launch_bounds__(256) k_agg2(float* __restrict__ out) {
    __shared__ float2 whos[128][8];      // Who j-tile (128 x 16 floats)
    __shared__ float e2ps[128], e2ns[128];
    __shared__ unsigned ms[32][4];
    __shared__ float vals[32][16];
    int r0 = blockIdx.x * 32;
    int t = threadIdx.x;
    int ty = t >> 3, tx = t & 7;         // ty: row (32), tx: c-pair (8)
    float2 acc = make_float2(0.f, 0.f);
    float den = 0.f;
    float e1p = g2_E1p[r0 + ty], e1n = g2_E1n[r0 + ty];

    for (int j0 = 0; j0 < N; j0 += 128) {
        for (int idx = t; idx < 128 * 16; idx += 256) {
            int j = idx >> 4, c = idx & 15;
            ((float*)whos)[j * 16 + c] = g_Who[(j0 + j) * C + c];
        }
        if (t < 128) {
            e2ps[t] = g2_E2p[j0 + t];
            e2ns[t] = g2_E2n[j0 + t];
        }
        if (t < 128) {
            int r = t >> 2, w = t & 3;
            ms[r][w] = g_mask[(r0 + r) * NW + (j0 >> 5) + w];
        }
        __syncthreads();
#pragma unroll 1
        for (int jw = 0; jw < 4; ++jw) {
            unsigned m = ms[ty][jw];
#pragma unroll
            for (int b = 0; b < 32; ++b) {
                int jj = jw * 32 + b;
                float e2p = e2ps[jj], e2n = e2ns[jj];
                float2 wv = whos[jj][tx];
                float wp = e1p * e2p;
                float wgt = (wp >= 1.f) ? wp : (e1n * e2n);
                wgt = ((m >> b) & 1u) ? wgt : 0.f;
                den += wgt;
                acc.x += wgt * wv.x;
                acc.y += wgt * wv.y;
            }
        }
        __syncthreads();
    }
    float inv = 1.f / den;
    float vx = acc.x * inv, vy = acc.y * inv;
    vx = (vx > 0.f) ? vx : (expf(vx) - 1.f);
    vy = (vy > 0.f) ? vy : (expf(vy) - 1.f);
    vals[ty][tx * 2] = vx;
    vals[ty][tx * 2 + 1] = vy;
    __syncthreads();
    if (t < 32) {
        float v[16];
        float mx = -1e30f;
#pragma unroll
        for (int c = 0; c < C; ++c) { v[c] = vals[t][c]; mx = fmaxf(mx, v[c]); }
        float s = 0.f;
#pragma unroll
        for (int c = 0; c < C; ++c) s += expf(v[c] - mx);
        float lse = mx + logf(s);
#pragma unroll
        for (int c = 0; c < C; ++c) out[(r0 + t) * C + c] = v[c] - lse;
    }
}

// ---------------- launch ----------------
extern "C" void kernel_launch(void* const* d_in, const int* in_sizes, int n_in,
                              void* d_out, int out_size) {
    const float* x    = (const float*)d_in[0];
    const int*   adj  = (const int*)d_in[1];
    const float* W    = (const float*)d_in[2];
    const float* a    = (const float*)d_in[3];
    const float* Wout = (const float*)d_in[4];
    const float* aout = (const float*)d_in[5];
    float* out = (float*)d_out;

    k_pack<<<N * NW / 8, 256>>>(adj);                 // 65536 blocks
    k_gemm1<<<dim3(N / 64, H), 256>>>(x, W);
    k_scores1<<<H * N / 8, 256>>>(a);
    k_agg1<<<dim3(N / 64, H), 256>>>();
    k_gemm2<<<N / 64, 256>>>(Wout);
    k_scores2<<<N / 8, 256>>>(aout);
    k_agg2<<<N / 32, 256>>>(out);
}